// round 13
// baseline (speedup 1.0000x reference)
#include <cuda_runtime.h>
#include <cuda_fp16.h>
#include <cstdint>

#define N_NODES 100000
#define N_EDGES 1600000
#define D 128
#define L 3
#define SCAN_BLKS ((N_NODES + 1023) / 1024)   // 98
#define NTILES ((N_NODES + 127) / 128)        // 782
#define GEMM_GRID 296                         // 2 blocks/SM * 148

// NOTE: all fp16 feature/weight rows store each 16-half group PERMUTED as
// [p0,p4,p1,p5,p2,p6,p3,p7] (p = half2 pair) so GEMM staging is a verbatim
// copy. Gather is element-wise and layout-agnostic.

// ---------------- scratch (device globals; no allocation allowed) ----------
__device__ __align__(16) __half g_hx  [N_NODES * D];
__device__ __align__(16) __half g_hagg[N_NODES * D];
__device__ __align__(16) __half g_hb0 [N_NODES * D];
__device__ __align__(16) __half g_hb1 [N_NODES * D];
__device__ __align__(16) __half g_hwl [L * D * D];
__device__ __align__(16) __half g_hwr [L * D * D];
__device__ int      g_cnt [N_NODES];
__device__ int      g_off [N_NODES + 1];
__device__ int      g_cur [N_NODES];
__device__ int      g_adj [N_EDGES];
__device__ int      g_bsum[128];
__device__ unsigned g_minbuf[D];

__device__ __forceinline__ unsigned f2mono(float f) {
    unsigned u = __float_as_uint(f);
    return (u & 0x80000000u) ? ~u : (u | 0x80000000u);
}
__device__ __forceinline__ float mono2f(unsigned m) {
    return (m & 0x80000000u) ? __uint_as_float(m ^ 0x80000000u)
                             : __uint_as_float(~m);
}
__device__ __forceinline__ uint32_t packh2(float a, float b) {
    __half2 h = __floats2half2_rn(a, b);
    return *(uint32_t*)&h;
}

// ---------------- f32 -> permuted fp16 conversion helper --------------------
__device__ __forceinline__ void conv16(const float* __restrict__ src,
                                       __half* __restrict__ dst) {
    float4 a = ((const float4*)src)[0];
    float4 b = ((const float4*)src)[1];
    float4 c = ((const float4*)src)[2];
    float4 d = ((const float4*)src)[3];
    uint32_t p0 = packh2(a.x, a.y), p1 = packh2(a.z, a.w);
    uint32_t p2 = packh2(b.x, b.y), p3 = packh2(b.z, b.w);
    uint32_t p4 = packh2(c.x, c.y), p5 = packh2(c.z, c.w);
    uint32_t p6 = packh2(d.x, d.y), p7 = packh2(d.z, d.w);
    ((uint4*)dst)[0] = make_uint4(p0, p4, p1, p5);
    ((uint4*)dst)[1] = make_uint4(p2, p6, p3, p7);
}

// ---------------- merged convert + degree histogram --------------------------
__global__ void k_ccnt(const float* __restrict__ x,
                       const float* __restrict__ Wl,
                       const float* __restrict__ Wr,
                       const int*   __restrict__ ei) {
    int g = blockIdx.x * blockDim.x + threadIdx.x;
    const int XG = N_NODES * D / 16;   // 800000
    const int WG = L * D * D / 16;     // 3072
    if (g < XG) {
        conv16(x + g * 16, g_hx + g * 16);
    } else if (g < XG + WG) {
        int h = g - XG;
        conv16(Wl + h * 16, g_hwl + h * 16);
    } else if (g < XG + 2 * WG) {
        int h = g - XG - WG;
        conv16(Wr + h * 16, g_hwr + h * 16);
    }
    if (g < N_EDGES / 4) {
        int4 d4 = ((const int4*)(ei + N_EDGES))[g];
        atomicAdd(&g_cnt[d4.x], 1);
        atomicAdd(&g_cnt[d4.y], 1);
        atomicAdd(&g_cnt[d4.z], 1);
        atomicAdd(&g_cnt[d4.w], 1);
    }
}

// ---------------- hierarchical scan -----------------------------------------
__global__ void __launch_bounds__(1024) k_scanA(void) {
    __shared__ int s[1024];
    int t = threadIdx.x;
    int i = blockIdx.x * 1024 + t;
    int v = (i < N_NODES) ? g_cnt[i] : 0;
    s[t] = v;
    __syncthreads();
    for (int o = 1; o < 1024; o <<= 1) {
        int u = (t >= o) ? s[t - o] : 0;
        __syncthreads();
        s[t] += u;
        __syncthreads();
    }
    if (i < N_NODES) g_off[i] = s[t] - v;
    if (t == 1023)   g_bsum[blockIdx.x] = s[t];
}

__global__ void k_scanB(void) {
    __shared__ int s[128];
    int t = threadIdx.x;
    int v = (t < SCAN_BLKS) ? g_bsum[t] : 0;
    s[t] = v;
    __syncthreads();
    for (int o = 1; o < 128; o <<= 1) {
        int u = (t >= o) ? s[t - o] : 0;
        __syncthreads();
        s[t] += u;
        __syncthreads();
    }
    if (t < SCAN_BLKS) g_bsum[t] = s[t] - v;
    if (t == 127)      g_off[N_NODES] = s[127];
}

__global__ void k_scanC(void) {
    int i = blockIdx.x * blockDim.x + threadIdx.x;
    if (i >= N_NODES) return;
    int o = g_off[i] + g_bsum[i >> 10];
    g_off[i] = o;
    g_cur[i] = o;
}

// ---------------- CSR fill (4 edges/thread) ---------------------------------
__global__ void k_fill(const int* __restrict__ ei) {
    int q = blockIdx.x * blockDim.x + threadIdx.x;
    if (q >= N_EDGES / 4) return;
    int4 s4 = ((const int4*)ei)[q];
    int4 d4 = ((const int4*)(ei + N_EDGES))[q];
    g_adj[atomicAdd(&g_cur[d4.x], 1)] = s4.x;
    g_adj[atomicAdd(&g_cur[d4.y], 1)] = s4.y;
    g_adj[atomicAdd(&g_cur[d4.z], 1)] = s4.z;
    g_adj[atomicAdd(&g_cur[d4.w], 1)] = s4.w;
}

// ---------------- per-layer mean gather: 16 lanes per node ------------------
__global__ void __launch_bounds__(256) k_gather(const __half* __restrict__ xcur) {
    int gid  = blockIdx.x * blockDim.x + threadIdx.x;
    int node = gid >> 4;
    int lane = threadIdx.x & 15;
    if (node >= N_NODES) return;

    int off0 = g_off[node];
    int off1 = g_off[node + 1];

    float4 accA = make_float4(0.f, 0.f, 0.f, 0.f);
    float4 accB = make_float4(0.f, 0.f, 0.f, 0.f);
    int i = off0;
    for (; i + 4 <= off1; i += 4) {
        int nb0 = g_adj[i + 0];
        int nb1 = g_adj[i + 1];
        int nb2 = g_adj[i + 2];
        int nb3 = g_adj[i + 3];
        uint4 u0 = ((const uint4*)(xcur + (long long)nb0 * D))[lane];
        uint4 u1 = ((const uint4*)(xcur + (long long)nb1 * D))[lane];
        uint4 u2 = ((const uint4*)(xcur + (long long)nb2 * D))[lane];
        uint4 u3 = ((const uint4*)(xcur + (long long)nb3 * D))[lane];
#pragma unroll
        for (int e = 0; e < 4; e++) {
            uint4 u = (e == 0) ? u0 : (e == 1) ? u1 : (e == 2) ? u2 : u3;
            float2 f0 = __half22float2(*(__half2*)&u.x);
            float2 f1 = __half22float2(*(__half2*)&u.y);
            float2 f2 = __half22float2(*(__half2*)&u.z);
            float2 f3 = __half22float2(*(__half2*)&u.w);
            accA.x += f0.x; accA.y += f0.y; accA.z += f1.x; accA.w += f1.y;
            accB.x += f2.x; accB.y += f2.y; accB.z += f3.x; accB.w += f3.y;
        }
    }
    for (; i < off1; i++) {
        int nb = g_adj[i];
        uint4 u = ((const uint4*)(xcur + (long long)nb * D))[lane];
        float2 f0 = __half22float2(*(__half2*)&u.x);
        float2 f1 = __half22float2(*(__half2*)&u.y);
        float2 f2 = __half22float2(*(__half2*)&u.z);
        float2 f3 = __half22float2(*(__half2*)&u.w);
        accA.x += f0.x; accA.y += f0.y; accA.z += f1.x; accA.w += f1.y;
        accB.x += f2.x; accB.y += f2.y; accB.z += f3.x; accB.w += f3.y;
    }
    float s = 1.0f / fmaxf((float)(off1 - off0), 1.0f);
    uint4 o;
    o.x = packh2(accA.x * s, accA.y * s);
    o.y = packh2(accA.z * s, accA.w * s);
    o.z = packh2(accB.x * s, accB.y * s);
    o.w = packh2(accB.z * s, accB.w * s);
    ((uint4*)(g_hagg + (long long)node * D))[lane] = o;
}

// ---------------- persistent fp16 GEMM, resident weights ---------------------
// Grid = 296 (2 blocks/SM). Each block loads ALL 8 B-chunks (Wl|Wr, 64KB
// payload) into smem once, then loops over 128-row tiles.
#define AS2 20
#define ATILE (128 * AS2)    // A tile words (2560)
#define BCH   (128 * AS2)    // B chunk words (2560)
#define GEMM_SMEM ((2 * ATILE + 8 * BCH + 128) * 4)   // 102912 bytes

__device__ __forceinline__ void mma_f16v(float* d, const uint32_t* a,
                                         uint32_t b0, uint32_t b1) {
    asm volatile(
        "mma.sync.aligned.m16n8k16.row.col.f32.f16.f16.f32 "
        "{%0,%1,%2,%3}, {%4,%5,%6,%7}, {%8,%9}, {%0,%1,%2,%3};"
        : "+f"(d[0]), "+f"(d[1]), "+f"(d[2]), "+f"(d[3])
        : "r"(a[0]), "r"(a[1]), "r"(a[2]), "r"(a[3]), "r"(b0), "r"(b1));
}

__device__ __forceinline__ void cp16(uint32_t smem_dst, const void* gmem_src) {
    asm volatile("cp.async.ca.shared.global [%0], [%1], 16;"
                 :: "r"(smem_dst), "l"(gmem_src));
}
__device__ __forceinline__ void cp_commit(void) {
    asm volatile("cp.async.commit_group;");
}
__device__ __forceinline__ void cp_wait0(void) {
    asm volatile("cp.async.wait_group 0;");
}

template<int RELU, int MINF>
__global__ void __launch_bounds__(256)
k_gemm(const __half* __restrict__ xcur,
       const __half* __restrict__ wl,
       const float*  __restrict__ bl,
       const __half* __restrict__ wr,
       __half* __restrict__ xnext) {
    extern __shared__ uint32_t smem[];
    uint32_t* AsBuf[2] = { smem, smem + ATILE };
    uint32_t* Ball = smem + 2 * ATILE;
    unsigned* sMin = (unsigned*)(smem + 2 * ATILE + 8 * BCH);

    int tid    = threadIdx.x;
    int wid    = tid >> 5;
    int lane   = tid & 31;
    int g      = lane >> 2;
    int c      = lane & 3;
    int warp_m = wid & 3;
    int warp_n = wid >> 2;

    int srow  = tid >> 1;
    int shalf = tid & 1;

    if (MINF && tid < 128) sMin[tid] = 0xFFFFFFFFu;

    // ---- stage ALL B chunks once (async) ----
#pragma unroll
    for (int kc = 0; kc < 8; kc++) {
        int kb = (kc & 3) * 32;
        const __half* bsrc = (kc < 4 ? wl : wr) + (long long)srow * D + kb + shalf * 16;
        uint32_t bdst = (uint32_t)__cvta_generic_to_shared(
            &Ball[kc * BCH + srow * AS2 + shalf * 8]);
        cp16(bdst,      bsrc);
        cp16(bdst + 16, (const char*)bsrc + 16);
    }
    cp_commit();
    cp_wait0();
    __syncthreads();

    uint32_t sA0 = (uint32_t)__cvta_generic_to_shared(&AsBuf[0][srow * AS2 + shalf * 8]);
    uint32_t sA1 = (uint32_t)__cvta_generic_to_shared(&AsBuf[1][srow * AS2 + shalf * 8]);

    for (int tile = blockIdx.x; tile < NTILES; tile += gridDim.x) {
        int blockRow = tile * 128;
        int arow = blockRow + srow;
        if (arow >= N_NODES) arow = N_NODES - 1;
        const __half* aBase0 = g_hagg + (long long)arow * D + shalf * 16;
        const __half* aBase1 = xcur   + (long long)arow * D + shalf * 16;

        __syncthreads();          // protect A buffers from previous tile's reads
        cp16(sA0,      aBase0);
        cp16(sA0 + 16, (const char*)aBase0 + 16);
        cp_commit();
        cp_wait0();
        __syncthreads();

        float acc[2][8][4];
#pragma unroll
        for (int mt = 0; mt < 2; mt++)
#pragma unroll
            for (int nt = 0; nt < 8; nt++)
#pragma unroll
                for (int r = 0; r < 4; r++) acc[mt][nt][r] = 0.f;

        for (int kc = 0; kc < 8; kc++) {
            int cb = kc & 1;
            if (kc < 7) {
                int nk = kc + 1;
                int kb = (nk & 3) * 32;
                const __half* asrc = (nk < 4 ? aBase0 : aBase1) + kb;
                uint32_t dst = (cb ^ 1) ? sA1 : sA0;
                cp16(dst,      asrc);
                cp16(dst + 16, (const char*)asrc + 16);
                cp_commit();
            }

            uint32_t* As = AsBuf[cb];
            uint32_t* Bs = Ball + kc * BCH;
#pragma unroll
            for (int ks = 0; ks < 2; ks++) {
                uint32_t a[2][4];
#pragma unroll
                for (int mt = 0; mt < 2; mt++) {
                    int row = warp_m * 32 + mt * 16 + g;
                    uint2 lo = *(uint2*)&As[row * AS2 + ks * 8 + 2 * c];
                    uint2 hi = *(uint2*)&As[(row + 8) * AS2 + ks * 8 + 2 * c];
                    a[mt][0] = lo.x; a[mt][1] = hi.x;
                    a[mt][2] = lo.y; a[mt][3] = hi.y;
                }
#pragma unroll
                for (int nt = 0; nt < 8; nt++) {
                    int col = warp_n * 64 + nt * 8 + g;
                    uint2 b = *(uint2*)&Bs[col * AS2 + ks * 8 + 2 * c];
                    mma_f16v(acc[0][nt], a[0], b.x, b.y);
                    mma_f16v(acc[1][nt], a[1], b.x, b.y);
                }
            }

            if (kc < 7) {
                cp_wait0();
                __syncthreads();
            }
        }

        // ---- per-tile epilogue ----
#pragma unroll
        for (int nt = 0; nt < 8; nt++) {
            int col = warp_n * 64 + nt * 8 + 2 * c;    // logical column
            float b0 = bl[col];
            float b1 = bl[col + 1];
            if (MINF) {
                float m0 = 3.4e38f, m1 = 3.4e38f;
#pragma unroll
                for (int mt = 0; mt < 2; mt++) {
                    int row0 = blockRow + warp_m * 32 + mt * 16 + g;
                    if (row0 < N_NODES) {
                        m0 = fminf(m0, acc[mt][nt][0] + b0);
                        m1 = fminf(m1, acc[mt][nt][1] + b1);
                    }
                    if (row0 + 8 < N_NODES) {
                        m0 = fminf(m0, acc[mt][nt][2] + b0);
                        m1 = fminf(m1, acc[mt][nt][3] + b1);
                    }
                }
#pragma unroll
                for (int s = 16; s >= 4; s >>= 1) {
                    m0 = fminf(m0, __shfl_xor_sync(0xFFFFFFFFu, m0, s));
                    m1 = fminf(m1, __shfl_xor_sync(0xFFFFFFFFu, m1, s));
                }
                if (g == 0) {
                    atomicMin(&sMin[col],     f2mono(m0));
                    atomicMin(&sMin[col + 1], f2mono(m1));
                }
            } else {
                // permuted store: pair q -> slot (q&~7)|((q&3)*2 + ((q>>2)&1))
                int q    = col >> 1;
                int slot = (q & ~7) | (((q & 3) << 1) | ((q >> 2) & 1));
#pragma unroll
                for (int mt = 0; mt < 2; mt++) {
                    int row0 = blockRow + warp_m * 32 + mt * 16 + g;
                    float v0 = acc[mt][nt][0] + b0;
                    float v1 = acc[mt][nt][1] + b1;
                    float v2 = acc[mt][nt][2] + b0;
                    float v3 = acc[mt][nt][3] + b1;
                    if (RELU) {
                        v0 = fmaxf(v0, 0.f); v1 = fmaxf(v1, 0.f);
                        v2 = fmaxf(v2, 0.f); v3 = fmaxf(v3, 0.f);
                    }
                    if (row0 < N_NODES)
                        ((uint32_t*)(xnext + (long long)row0 * D))[slot] = packh2(v0, v1);
                    if (row0 + 8 < N_NODES)
                        ((uint32_t*)(xnext + (long long)(row0 + 8) * D))[slot] = packh2(v2, v3);
                }
            }
        }
    }

    if (MINF) {
        __syncthreads();
        if (tid < 128) atomicMin(&g_minbuf[tid], sMin[tid]);
    }
}

// ---------------- final writeout --------------------------------------------
__global__ void k_writeout(float* __restrict__ out) {
    int j = threadIdx.x;
    out[j] = mono2f(g_minbuf[j]);
}

// ---------------- launch ----------------------------------------------------
extern "C" void kernel_launch(void* const* d_in, const int* in_sizes, int n_in,
                              void* d_out, int out_size) {
    const float* x  = (const float*)d_in[0];
    const int*   ei = (const int*)d_in[1];
    const float* Wl = (const float*)d_in[2];
    const float* bl = (const float*)d_in[3];
    const float* Wr = (const float*)d_in[4];
    float*       out = (float*)d_out;

    cudaFuncSetAttribute(k_gemm<1,0>, cudaFuncAttributeMaxDynamicSharedMemorySize, GEMM_SMEM);
    cudaFuncSetAttribute(k_gemm<0,1>, cudaFuncAttributeMaxDynamicSharedMemorySize, GEMM_SMEM);

    void *p_cnt, *p_min;
    cudaGetSymbolAddress(&p_cnt, g_cnt);
    cudaGetSymbolAddress(&p_min, g_minbuf);
    cudaMemsetAsync(p_cnt, 0, N_NODES * sizeof(int));
    cudaMemsetAsync(p_min, 0xFF, D * sizeof(unsigned));

    const int CONV_G = N_NODES * D / 16 + 2 * (L * D * D / 16);  // 806144

    k_ccnt  <<<(CONV_G + 255) / 256, 256>>>(x, Wl, Wr, ei);
    k_scanA <<<SCAN_BLKS, 1024>>>();
    k_scanB <<<1, 128>>>();
    k_scanC <<<(N_NODES + 255) / 256, 256>>>();
    k_fill  <<<(N_EDGES / 4 + 255) / 256, 256>>>(ei);

    __half* bufs[2];
    cudaGetSymbolAddress((void**)&bufs[0], g_hb0);
    cudaGetSymbolAddress((void**)&bufs[1], g_hb1);
    __half *hx, *hwl, *hwr;
    cudaGetSymbolAddress((void**)&hx,  g_hx);
    cudaGetSymbolAddress((void**)&hwl, g_hwl);
    cudaGetSymbolAddress((void**)&hwr, g_hwr);

    const int gatherBlocks = (N_NODES * 16 + 255) / 256;  // 6250

    const __half* cur = hx;
    for (int layer = 0; layer < L; layer++) {
        __half* nxt = bufs[layer & 1];
        k_gather<<<gatherBlocks, 256>>>(cur);
        const __half* wlp = hwl + (long long)layer * D * D;
        const __half* wrp = hwr + (long long)layer * D * D;
        const float*  b   = bl + (long long)layer * D;
        if (layer < L - 1)
            k_gemm<1,0><<<GEMM_GRID, 256, GEMM_SMEM>>>(cur, wlp, b, wrp, nxt);
        else
            k_gemm<0,1><<<GEMM_GRID, 256, GEMM_SMEM>>>(cur, wlp, b, wrp, nxt);
        cur = nxt;
    }

    k_writeout<<<1, D>>>(out);
}

// round 14
// speedup vs baseline: 1.0386x; 1.0386x over previous
#include <cuda_runtime.h>
#include <cuda_fp16.h>
#include <cstdint>

#define N_NODES 100000
#define N_EDGES 1600000
#define D 128
#define L 3
#define SCAN_BLKS ((N_NODES + 1023) / 1024)   // 98

// NOTE: all fp16 feature/weight rows store each 16-half group PERMUTED as
// [p0,p4,p1,p5,p2,p6,p3,p7] (p = half2 pair) so GEMM staging is a verbatim
// copy. Gather is element-wise and layout-agnostic.

// ---------------- scratch (device globals; no allocation allowed) ----------
__device__ __align__(16) __half g_hx  [N_NODES * D];
__device__ __align__(16) __half g_hagg[N_NODES * D];
__device__ __align__(16) __half g_hb0 [N_NODES * D];
__device__ __align__(16) __half g_hb1 [N_NODES * D];
__device__ __align__(16) __half g_hwl [L * D * D];
__device__ __align__(16) __half g_hwr [L * D * D];
__device__ int      g_cnt [N_NODES];
__device__ int      g_off [N_NODES + 1];
__device__ int      g_cur [N_NODES];
__device__ int      g_adj [N_EDGES];
__device__ int      g_bsum[128];
__device__ unsigned g_minbuf[D];

__device__ __forceinline__ unsigned f2mono(float f) {
    unsigned u = __float_as_uint(f);
    return (u & 0x80000000u) ? ~u : (u | 0x80000000u);
}
__device__ __forceinline__ float mono2f(unsigned m) {
    return (m & 0x80000000u) ? __uint_as_float(m ^ 0x80000000u)
                             : __uint_as_float(~m);
}
__device__ __forceinline__ uint32_t packh2(float a, float b) {
    __half2 h = __floats2half2_rn(a, b);
    return *(uint32_t*)&h;
}

// ---------------- f32 -> permuted fp16 conversion helper --------------------
__device__ __forceinline__ void conv16(const float* __restrict__ src,
                                       __half* __restrict__ dst) {
    float4 a = ((const float4*)src)[0];
    float4 b = ((const float4*)src)[1];
    float4 c = ((const float4*)src)[2];
    float4 d = ((const float4*)src)[3];
    uint32_t p0 = packh2(a.x, a.y), p1 = packh2(a.z, a.w);
    uint32_t p2 = packh2(b.x, b.y), p3 = packh2(b.z, b.w);
    uint32_t p4 = packh2(c.x, c.y), p5 = packh2(c.z, c.w);
    uint32_t p6 = packh2(d.x, d.y), p7 = packh2(d.z, d.w);
    ((uint4*)dst)[0] = make_uint4(p0, p4, p1, p5);
    ((uint4*)dst)[1] = make_uint4(p2, p6, p3, p7);
}

// ---------------- merged convert + degree histogram --------------------------
__global__ void k_ccnt(const float* __restrict__ x,
                       const float* __restrict__ Wl,
                       const float* __restrict__ Wr,
                       const int*   __restrict__ ei) {
    int g = blockIdx.x * blockDim.x + threadIdx.x;
    const int XG = N_NODES * D / 16;   // 800000
    const int WG = L * D * D / 16;     // 3072
    if (g < XG) {
        conv16(x + g * 16, g_hx + g * 16);
    } else if (g < XG + WG) {
        int h = g - XG;
        conv16(Wl + h * 16, g_hwl + h * 16);
    } else if (g < XG + 2 * WG) {
        int h = g - XG - WG;
        conv16(Wr + h * 16, g_hwr + h * 16);
    }
    if (g < N_EDGES / 4) {
        int4 d4 = ((const int4*)(ei + N_EDGES))[g];
        atomicAdd(&g_cnt[d4.x], 1);
        atomicAdd(&g_cnt[d4.y], 1);
        atomicAdd(&g_cnt[d4.z], 1);
        atomicAdd(&g_cnt[d4.w], 1);
    }
}

// ---------------- hierarchical scan -----------------------------------------
__global__ void __launch_bounds__(1024) k_scanA(void) {
    __shared__ int s[1024];
    int t = threadIdx.x;
    int i = blockIdx.x * 1024 + t;
    int v = (i < N_NODES) ? g_cnt[i] : 0;
    s[t] = v;
    __syncthreads();
    for (int o = 1; o < 1024; o <<= 1) {
        int u = (t >= o) ? s[t - o] : 0;
        __syncthreads();
        s[t] += u;
        __syncthreads();
    }
    if (i < N_NODES) g_off[i] = s[t] - v;
    if (t == 1023)   g_bsum[blockIdx.x] = s[t];
}

__global__ void k_scanB(void) {
    __shared__ int s[128];
    int t = threadIdx.x;
    int v = (t < SCAN_BLKS) ? g_bsum[t] : 0;
    s[t] = v;
    __syncthreads();
    for (int o = 1; o < 128; o <<= 1) {
        int u = (t >= o) ? s[t - o] : 0;
        __syncthreads();
        s[t] += u;
        __syncthreads();
    }
    if (t < SCAN_BLKS) g_bsum[t] = s[t] - v;
    if (t == 127)      g_off[N_NODES] = s[127];
}

__global__ void k_scanC(void) {
    int i = blockIdx.x * blockDim.x + threadIdx.x;
    if (i >= N_NODES) return;
    int o = g_off[i] + g_bsum[i >> 10];
    g_off[i] = o;
    g_cur[i] = o;
}

// ---------------- CSR fill (4 edges/thread) ---------------------------------
__global__ void k_fill(const int* __restrict__ ei) {
    int q = blockIdx.x * blockDim.x + threadIdx.x;
    if (q >= N_EDGES / 4) return;
    int4 s4 = ((const int4*)ei)[q];
    int4 d4 = ((const int4*)(ei + N_EDGES))[q];
    g_adj[atomicAdd(&g_cur[d4.x], 1)] = s4.x;
    g_adj[atomicAdd(&g_cur[d4.y], 1)] = s4.y;
    g_adj[atomicAdd(&g_cur[d4.z], 1)] = s4.z;
    g_adj[atomicAdd(&g_cur[d4.w], 1)] = s4.w;
}

// ---------------- per-layer mean gather: 16 lanes per node ------------------
__global__ void __launch_bounds__(256) k_gather(const __half* __restrict__ xcur) {
    int gid  = blockIdx.x * blockDim.x + threadIdx.x;
    int node = gid >> 4;
    int lane = threadIdx.x & 15;
    if (node >= N_NODES) return;

    int off0 = g_off[node];
    int off1 = g_off[node + 1];

    float4 accA = make_float4(0.f, 0.f, 0.f, 0.f);
    float4 accB = make_float4(0.f, 0.f, 0.f, 0.f);
    int i = off0;
    for (; i + 4 <= off1; i += 4) {
        int nb0 = g_adj[i + 0];
        int nb1 = g_adj[i + 1];
        int nb2 = g_adj[i + 2];
        int nb3 = g_adj[i + 3];
        uint4 u0 = ((const uint4*)(xcur + (long long)nb0 * D))[lane];
        uint4 u1 = ((const uint4*)(xcur + (long long)nb1 * D))[lane];
        uint4 u2 = ((const uint4*)(xcur + (long long)nb2 * D))[lane];
        uint4 u3 = ((const uint4*)(xcur + (long long)nb3 * D))[lane];
#pragma unroll
        for (int e = 0; e < 4; e++) {
            uint4 u = (e == 0) ? u0 : (e == 1) ? u1 : (e == 2) ? u2 : u3;
            float2 f0 = __half22float2(*(__half2*)&u.x);
            float2 f1 = __half22float2(*(__half2*)&u.y);
            float2 f2 = __half22float2(*(__half2*)&u.z);
            float2 f3 = __half22float2(*(__half2*)&u.w);
            accA.x += f0.x; accA.y += f0.y; accA.z += f1.x; accA.w += f1.y;
            accB.x += f2.x; accB.y += f2.y; accB.z += f3.x; accB.w += f3.y;
        }
    }
    for (; i < off1; i++) {
        int nb = g_adj[i];
        uint4 u = ((const uint4*)(xcur + (long long)nb * D))[lane];
        float2 f0 = __half22float2(*(__half2*)&u.x);
        float2 f1 = __half22float2(*(__half2*)&u.y);
        float2 f2 = __half22float2(*(__half2*)&u.z);
        float2 f3 = __half22float2(*(__half2*)&u.w);
        accA.x += f0.x; accA.y += f0.y; accA.z += f1.x; accA.w += f1.y;
        accB.x += f2.x; accB.y += f2.y; accB.z += f3.x; accB.w += f3.y;
    }
    float s = 1.0f / fmaxf((float)(off1 - off0), 1.0f);
    uint4 o;
    o.x = packh2(accA.x * s, accA.y * s);
    o.y = packh2(accA.z * s, accA.w * s);
    o.z = packh2(accB.x * s, accB.y * s);
    o.w = packh2(accB.z * s, accB.w * s);
    ((uint4*)(g_hagg + (long long)node * D))[lane] = o;
}

// ---------------- fp16 tensor-core fused SAGE GEMM (cp.async pipelined) ------
#define AS2 24
#define TILE_W (128 * AS2)   // words per matrix tile

__device__ __forceinline__ void mma_f16v(float* d, const uint32_t* a,
                                         uint32_t b0, uint32_t b1) {
    asm volatile(
        "mma.sync.aligned.m16n8k16.row.col.f32.f16.f16.f32 "
        "{%0,%1,%2,%3}, {%4,%5,%6,%7}, {%8,%9}, {%0,%1,%2,%3};"
        : "+f"(d[0]), "+f"(d[1]), "+f"(d[2]), "+f"(d[3])
        : "r"(a[0]), "r"(a[1]), "r"(a[2]), "r"(a[3]), "r"(b0), "r"(b1));
}

__device__ __forceinline__ void cp16(uint32_t smem_dst, const void* gmem_src) {
    asm volatile("cp.async.ca.shared.global [%0], [%1], 16;"
                 :: "r"(smem_dst), "l"(gmem_src));
}
__device__ __forceinline__ void cp_commit(void) {
    asm volatile("cp.async.commit_group;");
}
__device__ __forceinline__ void cp_wait0(void) {
    asm volatile("cp.async.wait_group 0;");
}

template<int RELU, int MINF>
__global__ void __launch_bounds__(256)
k_gemm(const __half* __restrict__ xcur,
       const __half* __restrict__ wl,
       const float*  __restrict__ bl,
       const __half* __restrict__ wr,
       __half* __restrict__ xnext) {
    extern __shared__ uint32_t smem[];
    uint32_t* AsBuf[2] = { smem,          smem + 2 * TILE_W };
    uint32_t* BsBuf[2] = { smem + TILE_W, smem + 3 * TILE_W };
    unsigned* sMin = (unsigned*)(smem + 4 * TILE_W);

    int tid    = threadIdx.x;
    int wid    = tid >> 5;
    int lane   = tid & 31;
    int g      = lane >> 2;
    int c      = lane & 3;
    int warp_m = wid & 3;
    int warp_n = wid >> 2;
    int blockRow = blockIdx.x * 128;

    if (MINF && tid < 128) sMin[tid] = 0xFFFFFFFFu;

    int srow  = tid >> 1;
    int shalf = tid & 1;
    int arow  = blockRow + srow;
    if (arow >= N_NODES) arow = N_NODES - 1;

    float acc[2][8][4];
#pragma unroll
    for (int mt = 0; mt < 2; mt++)
#pragma unroll
        for (int nt = 0; nt < 8; nt++)
#pragma unroll
            for (int r = 0; r < 4; r++) acc[mt][nt][r] = 0.f;

    const __half* aBase0 = g_hagg + (long long)arow * D + shalf * 16;
    const __half* aBase1 = xcur   + (long long)arow * D + shalf * 16;
    const __half* bBase0 = wl + (long long)srow * D + shalf * 16;
    const __half* bBase1 = wr + (long long)srow * D + shalf * 16;

    uint32_t sA[2], sB[2];
    sA[0] = (uint32_t)__cvta_generic_to_shared(&AsBuf[0][srow * AS2 + shalf * 8]);
    sA[1] = (uint32_t)__cvta_generic_to_shared(&AsBuf[1][srow * AS2 + shalf * 8]);
    sB[0] = (uint32_t)__cvta_generic_to_shared(&BsBuf[0][srow * AS2 + shalf * 8]);
    sB[1] = (uint32_t)__cvta_generic_to_shared(&BsBuf[1][srow * AS2 + shalf * 8]);

    // prefetch chunk 0
    cp16(sA[0],      aBase0);
    cp16(sA[0] + 16, (const char*)aBase0 + 16);
    cp16(sB[0],      bBase0);
    cp16(sB[0] + 16, (const char*)bBase0 + 16);
    cp_commit();
    cp_wait0();
    __syncthreads();

    for (int kc = 0; kc < 8; kc++) {
        int cb = kc & 1;
        if (kc < 7) {
            int nk = kc + 1;
            int kb = (nk & 3) * 32;   // halves
            const __half* asrc = (nk < 4 ? aBase0 : aBase1) + kb;
            const __half* bsrc = (nk < 4 ? bBase0 : bBase1) + kb;
            int nb = cb ^ 1;
            cp16(sA[nb],      asrc);
            cp16(sA[nb] + 16, (const char*)asrc + 16);
            cp16(sB[nb],      bsrc);
            cp16(sB[nb] + 16, (const char*)bsrc + 16);
            cp_commit();
        }

        uint32_t* As = AsBuf[cb];
        uint32_t* Bs = BsBuf[cb];
#pragma unroll
        for (int ks = 0; ks < 2; ks++) {
            uint32_t a[2][4];
#pragma unroll
            for (int mt = 0; mt < 2; mt++) {
                int row = warp_m * 32 + mt * 16 + g;
                uint2 lo = *(uint2*)&As[row * AS2 + ks * 8 + 2 * c];
                uint2 hi = *(uint2*)&As[(row + 8) * AS2 + ks * 8 + 2 * c];
                a[mt][0] = lo.x; a[mt][1] = hi.x;
                a[mt][2] = lo.y; a[mt][3] = hi.y;
            }
#pragma unroll
            for (int nt = 0; nt < 8; nt++) {
                int col = warp_n * 64 + nt * 8 + g;
                uint2 b = *(uint2*)&Bs[col * AS2 + ks * 8 + 2 * c];
                mma_f16v(acc[0][nt], a[0], b.x, b.y);
                mma_f16v(acc[1][nt], a[1], b.x, b.y);
            }
        }

        if (kc < 7) {
            cp_wait0();
            __syncthreads();
        }
    }

    // ---- epilogue ----
#pragma unroll
    for (int nt = 0; nt < 8; nt++) {
        int col = warp_n * 64 + nt * 8 + 2 * c;    // logical column
        float b0 = bl[col];
        float b1 = bl[col + 1];
        if (MINF) {
            float m0 = 3.4e38f, m1 = 3.4e38f;
#pragma unroll
            for (int mt = 0; mt < 2; mt++) {
                int row0 = blockRow + warp_m * 32 + mt * 16 + g;
                if (row0 < N_NODES) {
                    m0 = fminf(m0, acc[mt][nt][0] + b0);
                    m1 = fminf(m1, acc[mt][nt][1] + b1);
                }
                if (row0 + 8 < N_NODES) {
                    m0 = fminf(m0, acc[mt][nt][2] + b0);
                    m1 = fminf(m1, acc[mt][nt][3] + b1);
                }
            }
#pragma unroll
            for (int s = 16; s >= 4; s >>= 1) {
                m0 = fminf(m0, __shfl_xor_sync(0xFFFFFFFFu, m0, s));
                m1 = fminf(m1, __shfl_xor_sync(0xFFFFFFFFu, m1, s));
            }
            if (g == 0) {
                atomicMin(&sMin[col],     f2mono(m0));
                atomicMin(&sMin[col + 1], f2mono(m1));
            }
        } else {
            // permuted store: logical pair q -> slot (q&~7) | ((q&3)*2 + (q>>2)&1)
            int q    = col >> 1;
            int slot = (q & ~7) | (((q & 3) << 1) | ((q >> 2) & 1));
#pragma unroll
            for (int mt = 0; mt < 2; mt++) {
                int row0 = blockRow + warp_m * 32 + mt * 16 + g;
                float v0 = acc[mt][nt][0] + b0;
                float v1 = acc[mt][nt][1] + b1;
                float v2 = acc[mt][nt][2] + b0;
                float v3 = acc[mt][nt][3] + b1;
                if (RELU) {
                    v0 = fmaxf(v0, 0.f); v1 = fmaxf(v1, 0.f);
                    v2 = fmaxf(v2, 0.f); v3 = fmaxf(v3, 0.f);
                }
                if (row0 < N_NODES)
                    ((uint32_t*)(xnext + (long long)row0 * D))[slot] = packh2(v0, v1);
                if (row0 + 8 < N_NODES)
                    ((uint32_t*)(xnext + (long long)(row0 + 8) * D))[slot] = packh2(v2, v3);
            }
        }
    }

    if (MINF) {
        __syncthreads();
        if (tid < 128) atomicMin(&g_minbuf[tid], sMin[tid]);
    }
}

#define GEMM_SMEM ((4 * TILE_W + 128) * 4)   // 49664 bytes

// ---------------- final writeout --------------------------------------------
__global__ void k_writeout(float* __restrict__ out) {
    int j = threadIdx.x;
    out[j] = mono2f(g_minbuf[j]);
}

// ---------------- launch ----------------------------------------------------
extern "C" void kernel_launch(void* const* d_in, const int* in_sizes, int n_in,
                              void* d_out, int out_size) {
    const float* x  = (const float*)d_in[0];
    const int*   ei = (const int*)d_in[1];
    const float* Wl = (const float*)d_in[2];
    const float* bl = (const float*)d_in[3];
    const float* Wr = (const float*)d_in[4];
    float*       out = (float*)d_out;

    cudaFuncSetAttribute(k_gemm<1,0>, cudaFuncAttributeMaxDynamicSharedMemorySize, GEMM_SMEM);
    cudaFuncSetAttribute(k_gemm<0,1>, cudaFuncAttributeMaxDynamicSharedMemorySize, GEMM_SMEM);

    void *p_cnt, *p_min;
    cudaGetSymbolAddress(&p_cnt, g_cnt);
    cudaGetSymbolAddress(&p_min, g_minbuf);
    cudaMemsetAsync(p_cnt, 0, N_NODES * sizeof(int));
    cudaMemsetAsync(p_min, 0xFF, D * sizeof(unsigned));

    const int CONV_G = N_NODES * D / 16 + 2 * (L * D * D / 16);  // 806144

    k_ccnt  <<<(CONV_G + 255) / 256, 256>>>(x, Wl, Wr, ei);
    k_scanA <<<SCAN_BLKS, 1024>>>();
    k_scanB <<<1, 128>>>();
    k_scanC <<<(N_NODES + 255) / 256, 256>>>();
    k_fill  <<<(N_EDGES / 4 + 255) / 256, 256>>>(ei);

    __half* bufs[2];
    cudaGetSymbolAddress((void**)&bufs[0], g_hb0);
    cudaGetSymbolAddress((void**)&bufs[1], g_hb1);
    __half *hx, *hwl, *hwr;
    cudaGetSymbolAddress((void**)&hx,  g_hx);
    cudaGetSymbolAddress((void**)&hwl, g_hwl);
    cudaGetSymbolAddress((void**)&hwr, g_hwr);

    const int gemmBlocks   = (N_NODES + 127) / 128;       // 782
    const int gatherBlocks = (N_NODES * 16 + 255) / 256;  // 6250

    const __half* cur = hx;
    for (int layer = 0; layer < L; layer++) {
        __half* nxt = bufs[layer & 1];
        k_gather<<<gatherBlocks, 256>>>(cur);
        const __half* wlp = hwl + (long long)layer * D * D;
        const __half* wrp = hwr + (long long)layer * D * D;
        const float*  b   = bl + (long long)layer * D;
        if (layer < L - 1)
            k_gemm<1,0><<<gemmBlocks, 256, GEMM_SMEM>>>(cur, wlp, b, wrp, nxt);
        else
            k_gemm<0,1><<<gemmBlocks, 256, GEMM_SMEM>>>(cur, wlp, b, wrp, nxt);
        cur = nxt;
    }

    k_writeout<<<1, D>>>(out);
}